// round 15
// baseline (speedup 1.0000x reference)
#include <cuda_runtime.h>
#include <math.h>
#include <stdint.h>

// Problem constants
#define BATCH 2
#define NPTS 1024
#define NUM_BINS 22
#define TDIM 16
#define TSTRIDE 20           // padded table row stride (floats) for LDS conflicts
#define MAX_DIST 40.0f
#define LN_EPS 1e-5f

// ---------------------------------------------------------------------------
// Single fused kernel (ONE graph node), fully-parallel in-block table build:
//   Stage 1: each thread issues <=5 coalesced LDG.32 for its (bin,d) inputs.
//   Stage 2: Phase A (per-j bin offset + scale -> smem) hides stage-1 latency.
//   Stage 3: LN via 4-step shfl_xor butterfly in 16-lane segments.
//            Threads 0..95 own TWO bins (bin0 and bin0+16) with the two
//            butterfly chains INTERLEAVED in one loop (ILP overlaps SHFL
//            latency: ~250-cycle tail instead of ~420). Threads 96..255 run
//            the single chain for their bin0.
//   Phase B: LDS.64 broadcast + LDS.128 table row chunk,
//            2 packed f32x2 muls, STG.128.
// Grid (N/256, N, B) = 8192 blocks of 256.
// ---------------------------------------------------------------------------
__global__ __launch_bounds__(256)
void encode_kernel(const float* __restrict__ coords,
                   const float* __restrict__ conf,
                   const float* __restrict__ W,
                   const float* __restrict__ bb,
                   const float* __restrict__ gamma,
                   const float* __restrict__ beta,
                   float* __restrict__ out) {
    __shared__ float  sT[NUM_BINS * TSTRIDE];
    __shared__ float2 sP[256];    // (row byte-offset, scale) per local j

    const int tid    = threadIdx.x;
    const int i      = blockIdx.y;
    const int batch  = blockIdx.z;
    const int j_base = blockIdx.x * 256;

    // ---- Stage 1: issue table-input loads early (coalesced, few regs) ----
    const int d    = tid & 15;        // dim within row
    const int bin0 = tid >> 4;        // 0..15  (pass 0)
    float w0 = W[bin0 * TDIM + d];
    float w1 = 0.0f;
    if (tid < 96) w1 = W[(16 + bin0) * TDIM + d];   // second bin for warps 0..2
    const float bd = bb[d];
    const float gd = gamma[d];
    const float ed = beta[d];

    // ---- Stage 2: Phase A (all threads; hides stage-1 latency) ----
    {
        const float* ci_ptr = coords + ((size_t)batch * NPTS + i) * 3;
        const float xi = ci_ptr[0], yi = ci_ptr[1], zi = ci_ptr[2];
        const float ci = conf[batch * NPTS + i];

        const int j = j_base + tid;
        const float* cj_ptr = coords + ((size_t)batch * NPTS + j) * 3;
        const float dx = xi - cj_ptr[0];
        const float dy = yi - cj_ptr[1];
        const float dz = zi - cj_ptr[2];
        const float cj = conf[batch * NPTS + j];

        const float dist = sqrtf(fmaf(dx, dx, fmaf(dy, dy, fmaf(dz, dz, 1e-8f))));
        const float inv_w = (float)(NUM_BINS - 1) / MAX_DIST;  // 21/40

        int bin;
        if (ci > 0.0f && cj > 0.0f) {
            bin = (int)(dist * inv_w) + 1;          // #edges strictly below dist
            bin = (bin > NUM_BINS - 2) ? (NUM_BINS - 2) : bin;
        } else {
            bin = NUM_BINS - 1;
        }
        sP[tid] = make_float2(__int_as_float(bin * (TSTRIDE * 4)),
                              fminf(ci, cj));
    }

    // ---- Stage 3: parallel LN, dual-chain interleaved for warps 0..2 ----
    if (tid < 96) {
        const float h0 = w0 + bd;
        const float h1 = w1 + bd;
        float s0 = h0, q0 = h0 * h0;
        float s1 = h1, q1 = h1 * h1;
#pragma unroll
        for (int m = 1; m < 16; m <<= 1) {
            // independent chains: SHFL latencies overlap
            s0 += __shfl_xor_sync(0xFFFFFFFFu, s0, m);
            s1 += __shfl_xor_sync(0xFFFFFFFFu, s1, m);
            q0 += __shfl_xor_sync(0xFFFFFFFFu, q0, m);
            q1 += __shfl_xor_sync(0xFFFFFFFFu, q1, m);
        }
        {
            const float mu  = s0 * (1.0f / TDIM);
            const float var = fmaxf(q0 * (1.0f / TDIM) - mu * mu, 0.0f);
            const float inv = rsqrtf(var + LN_EPS);
            sT[bin0 * TSTRIDE + d] = fmaxf((h0 - mu) * inv * gd + ed, 0.0f);
        }
        {
            const float mu  = s1 * (1.0f / TDIM);
            const float var = fmaxf(q1 * (1.0f / TDIM) - mu * mu, 0.0f);
            const float inv = rsqrtf(var + LN_EPS);
            sT[(16 + bin0) * TSTRIDE + d] = fmaxf((h1 - mu) * inv * gd + ed, 0.0f);
        }
    } else {
        const float h = w0 + bd;
        float s = h, q = h * h;
#pragma unroll
        for (int m = 1; m < 16; m <<= 1) {
            s += __shfl_xor_sync(0xFFFFFFFFu, s, m);
            q += __shfl_xor_sync(0xFFFFFFFFu, q, m);
        }
        const float mu  = s * (1.0f / TDIM);
        const float var = fmaxf(q * (1.0f / TDIM) - mu * mu, 0.0f);
        const float inv = rsqrtf(var + LN_EPS);
        sT[bin0 * TSTRIDE + d] = fmaxf((h - mu) * inv * gd + ed, 0.0f);
    }
    __syncthreads();

    // ---- Phase B: gather + scale + store ----
    const int p = tid >> 2;   // pair slot within 64
    const int k = tid & 3;    // which float4 of the 16-vector

    float* optr = out + (((size_t)batch * NPTS + i) * NPTS + j_base + p) * TDIM + k * 4;
    const char* tbase = (const char*)sT + k * 16;

#pragma unroll
    for (int it = 0; it < 4; ++it) {
        const float2 pk = sP[it * 64 + p];      // broadcast within 4-lane group
        const int   off = __float_as_int(pk.x);
        const float sc  = pk.y;

        float4 v = *(const float4*)(tbase + off);

        // packed f32x2 multiplies: 2 instructions instead of 4
        uint64_t lo, hi, sv, rlo, rhi;
        asm("mov.b64 %0, {%1, %2};" : "=l"(sv) : "f"(sc), "f"(sc));
        asm("mov.b64 %0, {%1, %2};" : "=l"(lo) : "f"(v.x), "f"(v.y));
        asm("mov.b64 %0, {%1, %2};" : "=l"(hi) : "f"(v.z), "f"(v.w));
        asm("mul.rn.f32x2 %0, %1, %2;" : "=l"(rlo) : "l"(lo), "l"(sv));
        asm("mul.rn.f32x2 %0, %1, %2;" : "=l"(rhi) : "l"(hi), "l"(sv));
        float4 r;
        asm("mov.b64 {%0, %1}, %2;" : "=f"(r.x), "=f"(r.y) : "l"(rlo));
        asm("mov.b64 {%0, %1}, %2;" : "=f"(r.z), "=f"(r.w) : "l"(rhi));

        *(float4*)(optr + (size_t)it * 64 * TDIM) = r;
    }
}

// ---------------------------------------------------------------------------
// Launch: single kernel, single graph node.
// ---------------------------------------------------------------------------
extern "C" void kernel_launch(void* const* d_in, const int* in_sizes, int n_in,
                              void* d_out, int out_size) {
    const float* coords = (const float*)d_in[0];  // (B,N,3)
    const float* conf   = (const float*)d_in[1];  // (B,N)
    const float* W      = (const float*)d_in[2];  // (22,16)
    const float* b      = (const float*)d_in[3];  // (16,)
    const float* gamma  = (const float*)d_in[4];  // (16,)
    const float* beta   = (const float*)d_in[5];  // (16,)
    float* out = (float*)d_out;                   // (B,N,N,16)

    dim3 grid(NPTS / 256, NPTS, BATCH);
    encode_kernel<<<grid, 256>>>(coords, conf, W, b, gamma, beta, out);
}

// round 16
// speedup vs baseline: 1.1327x; 1.1327x over previous
#include <cuda_runtime.h>
#include <math.h>
#include <stdint.h>

// Problem constants
#define BATCH 2
#define NPTS 1024
#define NUM_BINS 22
#define TDIM 16
#define TSTRIDE 20           // padded table row stride (floats) for LDS conflicts
#define MAX_DIST 40.0f
#define LN_EPS 1e-5f

// ---------------------------------------------------------------------------
// Single fused kernel (ONE graph node). Each 256-thread block covers TWO
// i-rows x 256 j's (grid (N/256, N/2, B) = 4096 blocks): prologue amortized
// 2x and j-coord loads reused across both i's.
//   Stage 1: each thread issues <=5 coalesced LDG.32 for its (bin,d) inputs.
//   Stage 2: Phase A for i0 and i1 (shared j loads) -> sP[512].
//   Stage 3: LN via 4-step shfl_xor butterfly in 16-lane segments
//            (R14's measured-best form: pass 0 all threads, pass 1 tid<96).
//   Phase B: per i-row: LDS.64 broadcast + LDS.128 table chunk,
//            2 packed f32x2 muls, STG.128. 8 store iterations total.
// ---------------------------------------------------------------------------
__global__ __launch_bounds__(256)
void encode_kernel(const float* __restrict__ coords,
                   const float* __restrict__ conf,
                   const float* __restrict__ W,
                   const float* __restrict__ bb,
                   const float* __restrict__ gamma,
                   const float* __restrict__ beta,
                   float* __restrict__ out) {
    __shared__ float  sT[NUM_BINS * TSTRIDE];
    __shared__ float2 sP[512];    // (row byte-offset, scale), 2 i-rows x 256 j

    const int tid    = threadIdx.x;
    const int i0     = blockIdx.y * 2;
    const int batch  = blockIdx.z;
    const int j_base = blockIdx.x * 256;

    // ---- Stage 1: issue table-input loads early (coalesced, few regs) ----
    const int d    = tid & 15;        // dim within row
    const int bin0 = tid >> 4;        // 0..15  (pass 0)
    float w0 = W[bin0 * TDIM + d];
    float w1 = 0.0f;
    if (tid < 96) w1 = W[(16 + bin0) * TDIM + d];   // pass 1: bins 16..21
    const float bd = bb[d];
    const float gd = gamma[d];
    const float ed = beta[d];

    // ---- Stage 2: Phase A for both i-rows (j loads shared) ----
    {
        const int j = j_base + tid;
        const float* cj_ptr = coords + ((size_t)batch * NPTS + j) * 3;
        const float xj = cj_ptr[0], yj = cj_ptr[1], zj = cj_ptr[2];
        const float cj = conf[batch * NPTS + j];
        const float inv_w = (float)(NUM_BINS - 1) / MAX_DIST;  // 21/40

#pragma unroll
        for (int ii = 0; ii < 2; ++ii) {
            const int i = i0 + ii;
            const float* ci_ptr = coords + ((size_t)batch * NPTS + i) * 3;
            const float xi = ci_ptr[0], yi = ci_ptr[1], zi = ci_ptr[2];
            const float ci = conf[batch * NPTS + i];

            const float dx = xi - xj;
            const float dy = yi - yj;
            const float dz = zi - zj;
            const float dist =
                sqrtf(fmaf(dx, dx, fmaf(dy, dy, fmaf(dz, dz, 1e-8f))));

            int bin;
            if (ci > 0.0f && cj > 0.0f) {
                bin = (int)(dist * inv_w) + 1;      // #edges strictly below dist
                bin = (bin > NUM_BINS - 2) ? (NUM_BINS - 2) : bin;
            } else {
                bin = NUM_BINS - 1;
            }
            sP[ii * 256 + tid] = make_float2(__int_as_float(bin * (TSTRIDE * 4)),
                                             fminf(ci, cj));
        }
    }

    // ---- Stage 3: parallel LN (R14's measured-best two-pass form) ----
    {
        const float h = w0 + bd;
        float s = h, q = h * h;
#pragma unroll
        for (int m = 1; m < 16; m <<= 1) {
            s += __shfl_xor_sync(0xFFFFFFFFu, s, m);
            q += __shfl_xor_sync(0xFFFFFFFFu, q, m);
        }
        const float mu  = s * (1.0f / TDIM);
        const float var = fmaxf(q * (1.0f / TDIM) - mu * mu, 0.0f);
        const float inv = rsqrtf(var + LN_EPS);
        sT[bin0 * TSTRIDE + d] = fmaxf((h - mu) * inv * gd + ed, 0.0f);
    }
    if (tid < 96) {
        const float h = w1 + bd;
        float s = h, q = h * h;
#pragma unroll
        for (int m = 1; m < 16; m <<= 1) {
            s += __shfl_xor_sync(0xFFFFFFFFu, s, m);
            q += __shfl_xor_sync(0xFFFFFFFFu, q, m);
        }
        const float mu  = s * (1.0f / TDIM);
        const float var = fmaxf(q * (1.0f / TDIM) - mu * mu, 0.0f);
        const float inv = rsqrtf(var + LN_EPS);
        sT[(16 + bin0) * TSTRIDE + d] = fmaxf((h - mu) * inv * gd + ed, 0.0f);
    }
    __syncthreads();

    // ---- Phase B: gather + scale + store (both i-rows) ----
    const int p = tid >> 2;   // pair slot within 64
    const int k = tid & 3;    // which float4 of the 16-vector
    const char* tbase = (const char*)sT + k * 16;

#pragma unroll
    for (int ii = 0; ii < 2; ++ii) {
        float* optr = out +
            (((size_t)batch * NPTS + (i0 + ii)) * NPTS + j_base + p) * TDIM + k * 4;

#pragma unroll
        for (int it = 0; it < 4; ++it) {
            const float2 pk = sP[ii * 256 + it * 64 + p];  // 4-lane broadcast
            const int   off = __float_as_int(pk.x);
            const float sc  = pk.y;

            float4 v = *(const float4*)(tbase + off);

            // packed f32x2 multiplies: 2 instructions instead of 4
            uint64_t lo, hi, sv, rlo, rhi;
            asm("mov.b64 %0, {%1, %2};" : "=l"(sv) : "f"(sc), "f"(sc));
            asm("mov.b64 %0, {%1, %2};" : "=l"(lo) : "f"(v.x), "f"(v.y));
            asm("mov.b64 %0, {%1, %2};" : "=l"(hi) : "f"(v.z), "f"(v.w));
            asm("mul.rn.f32x2 %0, %1, %2;" : "=l"(rlo) : "l"(lo), "l"(sv));
            asm("mul.rn.f32x2 %0, %1, %2;" : "=l"(rhi) : "l"(hi), "l"(sv));
            float4 r;
            asm("mov.b64 {%0, %1}, %2;" : "=f"(r.x), "=f"(r.y) : "l"(rlo));
            asm("mov.b64 {%0, %1}, %2;" : "=f"(r.z), "=f"(r.w) : "l"(rhi));

            *(float4*)(optr + (size_t)it * 64 * TDIM) = r;
        }
    }
}

// ---------------------------------------------------------------------------
// Launch: single kernel, single graph node.
// ---------------------------------------------------------------------------
extern "C" void kernel_launch(void* const* d_in, const int* in_sizes, int n_in,
                              void* d_out, int out_size) {
    const float* coords = (const float*)d_in[0];  // (B,N,3)
    const float* conf   = (const float*)d_in[1];  // (B,N)
    const float* W      = (const float*)d_in[2];  // (22,16)
    const float* b      = (const float*)d_in[3];  // (16,)
    const float* gamma  = (const float*)d_in[4];  // (16,)
    const float* beta   = (const float*)d_in[5];  // (16,)
    float* out = (float*)d_out;                   // (B,N,N,16)

    dim3 grid(NPTS / 256, NPTS / 2, BATCH);
    encode_kernel<<<grid, 256>>>(coords, conf, W, b, gamma, beta, out);
}